// round 13
// baseline (speedup 1.0000x reference)
#include <cuda_runtime.h>
#include <cuda_bf16.h>
#include <math.h>

// Problem constants (fixed shapes): B=16, N=2000, C=512, H=W=7
#define Bn 16
#define Nn 2000
#define Dn 25088            // 512*7*7
#define PI2F ((float)(3.14159 / 2.0))   // matches reference constant exactly
#define CHUNK 128           // floats per d-chunk in k_dots
#define DSPLIT 7            // d-split for k_dots
#define CPB 28              // chunks per block = (25088/128)/7
#define KSLOT 6             // k_dots smem slots (3 pairs), 96KB
#define RSTG 12             // k_read pipeline stages

// ---- device scratch (static allocation only; no cudaMalloc allowed) ----
__device__ float  g_dotp[DSPLIT * Bn * Nn];  // partial dots per d-split, [p][b][n]
__device__ float  g_sqp[DSPLIT * Nn];        // partial row sumsq per d-split, [p][n]
__device__ float  g_kps[Bn * DSPLIT];        // key sum partials, [b][sy]
__device__ float  g_kpq[Bn * DSPLIT];        // key sumsq partials, [b][sy]
__device__ __align__(16) float2 g_w2[Nn * Bn];  // weights, [n][b], duplicated (w,w)

// ---- packed fp32x2 FMA (sm_100+; ptxas will not auto-generate this) ----
__device__ __forceinline__ void fma2(unsigned long long& acc,
                                     unsigned long long a,
                                     unsigned long long b) {
    asm("fma.rn.f32x2 %0, %1, %2, %0;" : "+l"(acc) : "l"(a), "l"(b));
}
__device__ __forceinline__ float f2lo(unsigned long long v) {
    return __uint_as_float((unsigned)(v & 0xFFFFFFFFull));
}
__device__ __forceinline__ float f2hi(unsigned long long v) {
    return __uint_as_float((unsigned)(v >> 32));
}

// ---- cp.async (LDGSTS) helpers ----
__device__ __forceinline__ void cp16(void* smem, const void* gmem) {
    unsigned s = (unsigned)__cvta_generic_to_shared(smem);
    asm volatile("cp.async.cg.shared.global [%0], [%1], 16;" :: "r"(s), "l"(gmem));
}
__device__ __forceinline__ void cp_commit() {
    asm volatile("cp.async.commit_group;");
}
template <int N>
__device__ __forceinline__ void cp_wait() {
    asm volatile("cp.async.wait_group %0;" :: "n"(N));
}

// ---- no-return vector atomic add ----
__device__ __forceinline__ void red_add4(float* p, float x, float y, float z, float w) {
    asm volatile("red.global.add.v4.f32 [%0], {%1, %2, %3, %4};"
                 :: "l"(p), "f"(x), "f"(y), "f"(z), "f"(w) : "memory");
}

// =======================================================================
// K2: partial dots + partial sumsq (+ fused key stats in x==0 blocks).
// grid (125, 7) x 256 threads. Block owns 16 memory rows, 28 d-chunks of
// 128 floats (d-split by grid.y). Key chunk (16x128) + mem chunk (16x128)
// per slot; 6 slots = 3 pairs in a ring. ONE barrier per pair (14 total):
//   wait<2> (pair p landed) -> barrier -> fill pair p+2's slots (consumed
//   at iter p-1; safe) -> compute both chunks.
// Dynamic smem: 6 x 16KB = 96KB; 2 blocks/SM (192KB).
// Lane layout per warp: bit7=bh (which 8 b's), bits[6:5]=u_hi, bits[4:3]=g
// (which 4 n's), bits[2:0]=u_lo. d-lane = u_hi*8+u_lo (4 floats each).
// g in-warp -> key LDS is a 4-way in-warp broadcast.
// =======================================================================
__global__ __launch_bounds__(256, 2) void k_dots(const float* __restrict__ key,
                                                 const float* __restrict__ mem) {
    extern __shared__ __align__(16) float sdyn[];   // KSLOT * 4096 floats
    // overlay after the chunk loop: reduction scratch on slot 0
    float* sred = sdyn;          // 256 floats [bh][g][bb][r]
    float* ssq  = sdyn + 256;    // 16 floats  [g][r]

    int tid  = threadIdx.x;
    int bh   = tid >> 7;
    int g    = (tid >> 3) & 3;
    int u_lo = tid & 7;
    int dl   = ((tid >> 5) & 3) * 8 + u_lo;   // d-lane 0..31
    int nb   = blockIdx.x * 16;
    int sy   = blockIdx.y;
    int cbase = sy * CPB;
    bool bx0 = (blockIdx.x == 0);

    unsigned long long acc[8][4];
    #pragma unroll
    for (int i = 0; i < 8; ++i)
        #pragma unroll
        for (int r = 0; r < 4; ++r) acc[i][r] = 0ull;
    unsigned long long sq2[4] = {0ull, 0ull, 0ull, 0ull};
    float ks = 0.f, kq = 0.f;    // fused key stats (x==0 blocks only)

    // staging lanes: thread copies one float4 of 2 key rows + 2 mem rows
    int row0 = tid >> 5;          // 0..7
    int j    = tid & 31;          // float4 within row

    // induction-variable global pointers (advance by 2*CHUNK per pair)
    const float* pk0 = key + (size_t)row0 * Dn + j * 4 + cbase * CHUNK;
    const float* pk1 = key + (size_t)(row0 + 8) * Dn + j * 4 + cbase * CHUNK;
    const float* pm0 = mem + (size_t)(nb + row0) * Dn + j * 4 + cbase * CHUNK;
    const float* pm1 = mem + (size_t)(nb + row0 + 8) * Dn + j * 4 + cbase * CHUNK;

    int so  = row0 * CHUNK + j * 4;        // smem float offset (rows 0..7)
    int so8 = (row0 + 8) * CHUNK + j * 4;  // smem float offset (rows 8..15)

    // per-thread constant compute offsets
    int mvoff = g * 4 * CHUNK + dl * 4;    // + r*CHUNK (const) inside
    int kvoff = bh * 8 * CHUNK + dl * 4;   // + bb*CHUNK (const) inside
    int ksoff = (tid >> 4) * CHUNK + (tid & 15) * 8;

    // prologue: chunks 0..3 into slots 0..3 (one commit per chunk)
    #pragma unroll
    for (int s = 0; s < 4; ++s) {
        float* st = sdyn + s * 4096;
        cp16(st + so,         pk0 + s * CHUNK);
        cp16(st + so8,        pk1 + s * CHUNK);
        cp16(st + 2048 + so,  pm0 + s * CHUNK);
        cp16(st + 2048 + so8, pm1 + s * CHUNK);
        cp_commit();
    }

    int sb0 = 0;   // slot of this pair's even chunk: cycles 0 -> 2 -> 4 -> 0
    #pragma unroll 1
    for (int p = 0; p < 14; ++p) {
        cp_wait<2>();          // chunks 2p, 2p+1 landed (commit accounting)
        __syncthreads();       // visible to all; fill-target pair's reads done

        // fill pair p+2 (chunks 2p+4, 2p+5) into slots f0, f0+1
        int f0 = (sb0 == 0) ? 4 : sb0 - 2;
        if (p < 12) {
            float* st = sdyn + f0 * 4096;
            cp16(st + so,         pk0 + 4 * CHUNK);
            cp16(st + so8,        pk1 + 4 * CHUNK);
            cp16(st + 2048 + so,  pm0 + 4 * CHUNK);
            cp16(st + 2048 + so8, pm1 + 4 * CHUNK);
        }
        cp_commit();           // unconditional: keeps group accounting
        if (p < 12) {
            float* st = sdyn + (f0 + 1) * 4096;
            cp16(st + so,         pk0 + 5 * CHUNK);
            cp16(st + so8,        pk1 + 5 * CHUNK);
            cp16(st + 2048 + so,  pm0 + 5 * CHUNK);
            cp16(st + 2048 + so8, pm1 + 5 * CHUNK);
        }
        cp_commit();

        // compute both chunks of the pair, back to back
        #pragma unroll
        for (int h = 0; h < 2; ++h) {
            const float* km = sdyn + (sb0 + h) * 4096;
            const float* mm = km + 2048;

            ulonglong2 mv[4];
            #pragma unroll
            for (int r = 0; r < 4; ++r)
                mv[r] = *(const ulonglong2*)&mm[mvoff + r * CHUNK];
            if (bh == 0) {
                #pragma unroll
                for (int r = 0; r < 4; ++r) {
                    fma2(sq2[r], mv[r].x, mv[r].x);
                    fma2(sq2[r], mv[r].y, mv[r].y);
                }
            }
            #pragma unroll
            for (int bb = 0; bb < 8; ++bb) {
                ulonglong2 kv = *(const ulonglong2*)&km[kvoff + bb * CHUNK];
                #pragma unroll
                for (int r = 0; r < 4; ++r) {
                    fma2(acc[bb][r], kv.x, mv[r].x);
                    fma2(acc[bb][r], kv.y, mv[r].y);
                }
            }
            if (bx0) {   // fused key stats: thread covers b=tid>>4, 8 d-floats
                const float* kc = km + ksoff;
                float4 v0 = *(const float4*)kc;
                float4 v1 = *(const float4*)(kc + 4);
                ks += (v0.x + v0.y) + (v0.z + v0.w) + (v1.x + v1.y) + (v1.z + v1.w);
                kq = fmaf(v0.x, v0.x, kq); kq = fmaf(v0.y, v0.y, kq);
                kq = fmaf(v0.z, v0.z, kq); kq = fmaf(v0.w, v0.w, kq);
                kq = fmaf(v1.x, v1.x, kq); kq = fmaf(v1.y, v1.y, kq);
                kq = fmaf(v1.z, v1.z, kq); kq = fmaf(v1.w, v1.w, kq);
            }
        }

        pk0 += 2 * CHUNK; pk1 += 2 * CHUNK;
        pm0 += 2 * CHUNK; pm1 += 2 * CHUNK;
        sb0 += 2; if (sb0 == KSLOT) sb0 = 0;
    }
    __syncthreads();   // all data groups drained; safe to overlay slot 0
    sred[tid] = 0.f;   // zero overlaid reduction scratch (sred[256] + ssq[16])
    if (tid < 16) ssq[tid] = 0.f;
    __syncthreads();

    // key-stat reduce within 16-lane half-warps (same b), write per-sy partial
    if (bx0) {
        #pragma unroll
        for (int o = 1; o < 16; o <<= 1) {
            ks += __shfl_xor_sync(0xFFFFFFFFu, ks, o);
            kq += __shfl_xor_sync(0xFFFFFFFFu, kq, o);
        }
        if ((tid & 15) == 0) {
            g_kps[(tid >> 4) * DSPLIT + sy] = ks;
            g_kpq[(tid >> 4) * DSPLIT + sy] = kq;
        }
    }

    // reduce: butterfly over u_lo (8 lanes), then smem-atomic across 4 u_hi warps
    #pragma unroll
    for (int bb = 0; bb < 8; ++bb)
        #pragma unroll
        for (int r = 0; r < 4; ++r) {
            float v = f2lo(acc[bb][r]) + f2hi(acc[bb][r]);
            v += __shfl_xor_sync(0xFFFFFFFFu, v, 1);
            v += __shfl_xor_sync(0xFFFFFFFFu, v, 2);
            v += __shfl_xor_sync(0xFFFFFFFFu, v, 4);
            if (bb == u_lo)
                atomicAdd(&sred[bh * 128 + g * 32 + bb * 4 + r], v);
        }
    if (bh == 0) {
        #pragma unroll
        for (int r = 0; r < 4; ++r) {
            float v = f2lo(sq2[r]) + f2hi(sq2[r]);
            v += __shfl_xor_sync(0xFFFFFFFFu, v, 1);
            v += __shfl_xor_sync(0xFFFFFFFFu, v, 2);
            v += __shfl_xor_sync(0xFFFFFFFFu, v, 4);
            if (u_lo == r) atomicAdd(&ssq[g * 4 + r], v);
        }
    }
    __syncthreads();

    {   // write 256 partial dots
        int r = tid & 3, bb = (tid >> 2) & 7, gg = (tid >> 5) & 3, b2 = tid >> 7;
        int b = b2 * 8 + bb, n = nb + gg * 4 + r;
        g_dotp[((size_t)sy * Bn + b) * Nn + n] = sred[b2 * 128 + gg * 32 + bb * 4 + r];
    }
    if (tid < 16) {
        int r = tid & 3, gg = tid >> 2;
        g_sqp[(size_t)sy * Nn + nb + gg * 4 + r] = ssq[gg * 4 + r];
    }
}

// ============================================================
// K3: sum partials -> cos -> tan -> softmax; write transposed
// duplicated weights (w,w). Also zeroes d_out (replaces memset;
// runs before k_read in-stream). grid 16 x 256.
// ============================================================
__global__ void k_softmax(float* __restrict__ out) {
    int b = blockIdx.x, tid = threadIdx.x;
    __shared__ float sbuf[256];
    __shared__ float s_kfac;

    // zero this block's slice of the output (Bn*Dn floats over 16 blocks)
    {
        float4 z = make_float4(0.f, 0.f, 0.f, 0.f);
        float4* o4 = (float4*)(out + (size_t)b * Dn);
        for (int i = tid; i < Dn / 4; i += 256) o4[i] = z;
    }

    if (tid == 0) {
        float S = 0.f, Q = 0.f;
        #pragma unroll
        for (int p = 0; p < DSPLIT; ++p) {
            S += g_kps[b * DSPLIT + p];
            Q += g_kpq[b * DSPLIT + p];
        }
        S += 1e-7f;                                   // EPS_SUM
        // (s+eps)*kn = max(sqrt(sq_key), 1e-8*(s+eps))
        s_kfac = 1.f / fmaxf(sqrtf(Q), 1e-8f * S);
    }
    __syncthreads();
    float kf = s_kfac;

    float tv[8];
    float mx = -3.4e38f;
    #pragma unroll
    for (int i = 0; i < 8; ++i) {
        int n = tid + i * 256;
        if (n < Nn) {
            float dot = 0.f, sqv = 0.f;
            #pragma unroll
            for (int p = 0; p < DSPLIT; ++p) {
                dot += g_dotp[((size_t)p * Bn + b) * Nn + n];
                sqv += g_sqp[(size_t)p * Nn + n];
            }
            float mn = fmaxf(sqrtf(sqv), 1e-8f);
            float cosv = dot * kf / mn;
            float t = tanf(cosv * PI2F);
            tv[i] = t;
            mx = fmaxf(mx, t);
        } else tv[i] = -3.4e38f;
    }
    sbuf[tid] = mx; __syncthreads();
    for (int s = 128; s; s >>= 1) {
        if (tid < s) sbuf[tid] = fmaxf(sbuf[tid], sbuf[tid + s]);
        __syncthreads();
    }
    mx = sbuf[0];
    __syncthreads();

    float sum = 0.f;
    #pragma unroll
    for (int i = 0; i < 8; ++i) {
        int n = tid + i * 256;
        if (n < Nn) { float e = expf(tv[i] - mx); tv[i] = e; sum += e; }
    }
    sbuf[tid] = sum; __syncthreads();
    for (int s = 128; s; s >>= 1) {
        if (tid < s) sbuf[tid] += sbuf[tid + s];
        __syncthreads();
    }
    float inv = 1.f / sbuf[0];

    #pragma unroll
    for (int i = 0; i < 8; ++i) {
        int n = tid + i * 256;
        if (n < Nn) {
            float w = tv[i] * inv;
            g_w2[(size_t)n * Bn + b] = make_float2(w, w);  // pre-duplicated pair
        }
    }
}

// =======================================================================
// K4: out[b][d] = sum_n w[b][n] * mem[n][d]. grid (49, 15) x 128 threads.
// 735 blocks vs 740 occ-5 slots on 148 SMs = 0.99 waves.
// Thread owns 4 consecutive d; 16 b accumulators as f32x2 pairs.
// Mem rows flow through a per-thread 12-stage cp.async pipeline (11 rows of
// DRAM latency in flight, no barriers). Weight tile staged in smem once.
// Partials combined via red.global.add.v4.f32 (no-return vector atomic).
// =======================================================================
__global__ __launch_bounds__(128, 5) void k_read(const float* __restrict__ mem,
                                                 float* __restrict__ out) {
    __shared__ __align__(16) ulonglong2 sw[134 * 8];     // 17152 B weight tile
    __shared__ __align__(16) char smrow[RSTG][2048];     // 24 KB pipeline

    int tid = threadIdx.x;
    int d   = blockIdx.x * 512 + tid * 4;
    int y   = blockIdx.y;
    // 2000 = 5 tiles of 134 + 10 tiles of 133
    int n0  = (y < 5) ? y * 134 : 670 + (y - 5) * 133;
    int cnt = (y < 5) ? 134 : 133;

    // stage weight tile: cnt x 128B
    {
        const float4* src = (const float4*)(g_w2 + (size_t)n0 * Bn);
        for (int i = tid; i < cnt * 8; i += 128)
            ((float4*)sw)[i] = src[i];
    }

    unsigned long long acc[16][2];
    #pragma unroll
    for (int b = 0; b < 16; ++b) { acc[b][0] = 0ull; acc[b][1] = 0ull; }

    const float* mp = mem + (size_t)n0 * Dn + d;
    // prologue: 11 rows in flight (cnt >= 133 always)
    #pragma unroll
    for (int s = 0; s < RSTG - 1; ++s) {
        cp16(&smrow[s][tid * 16], mp + (size_t)s * Dn);
        cp_commit();
    }
    const float* pf = mp + (size_t)(RSTG - 1) * Dn;
    __syncthreads();   // weight tile ready

    int slc = 0, sli = RSTG - 1;
    for (int n = 0; n < cnt; ++n) {
        cp_wait<RSTG - 2>();  // per-thread: stage n landed
        ulonglong2 cur = *(const ulonglong2*)&smrow[slc][tid * 16];
        if (++slc == RSTG) slc = 0;
        if (n + RSTG - 1 < cnt) cp16(&smrow[sli][tid * 16], pf);
        cp_commit();
        if (++sli == RSTG) sli = 0;
        pf += Dn;
        const ulonglong2* wq = sw + n * 8;
        #pragma unroll
        for (int q = 0; q < 8; ++q) {
            ulonglong2 wv = wq[q];                // (w2q,w2q),(w2q+1,w2q+1)
            fma2(acc[2 * q    ][0], wv.x, cur.x);
            fma2(acc[2 * q    ][1], wv.x, cur.y);
            fma2(acc[2 * q + 1][0], wv.y, cur.x);
            fma2(acc[2 * q + 1][1], wv.y, cur.y);
        }
    }

    #pragma unroll
    for (int b = 0; b < 16; ++b) {
        float* o = out + (size_t)b * Dn + d;
        red_add4(o, f2lo(acc[b][0]), f2hi(acc[b][0]),
                    f2lo(acc[b][1]), f2hi(acc[b][1]));
    }
}

// ============================================================
extern "C" void kernel_launch(void* const* d_in, const int* in_sizes, int n_in,
                              void* d_out, int out_size) {
    const float* key = (const float*)d_in[0];
    const float* mem = (const float*)d_in[1];
    // metadata order is key, memory; swap defensively if sizes say otherwise
    if (n_in >= 2 && in_sizes[0] == Nn * Dn) {
        key = (const float*)d_in[1];
        mem = (const float*)d_in[0];
    }
    float* out = (float*)d_out;

    // 96KB dynamic smem for k_dots (attribute persists from the harness's
    // non-captured correctness call, so capture-time behavior is identical)
    const int kdots_smem = KSLOT * 4096 * (int)sizeof(float);
    cudaFuncSetAttribute(k_dots, cudaFuncAttributeMaxDynamicSharedMemorySize,
                         kdots_smem);

    k_dots<<<dim3(125, DSPLIT), 256, kdots_smem>>>(key, mem);
    k_softmax<<<16, 256>>>(out);   // also zeroes out before k_read's red.adds
    k_read<<<dim3(49, 15), 128>>>(mem, out);
}

// round 14
// speedup vs baseline: 1.6818x; 1.6818x over previous
#include <cuda_runtime.h>
#include <cuda_bf16.h>
#include <math.h>

// Problem constants (fixed shapes): B=16, N=2000, C=512, H=W=7
#define Bn 16
#define Nn 2000
#define Dn 25088            // 512*7*7
#define PI2F ((float)(3.14159 / 2.0))   // matches reference constant exactly
#define CHUNK 256           // floats per d-chunk in k_dots
#define DSPLIT 7            // d-split for k_dots
#define CPB 14              // chunks per block = (25088/256)/7
#define KSLOT 3             // k_dots pipeline slots (32KB each = 96KB)
#define SLOTF 8192          // floats per slot (16*256 key + 16*256 mem)
#define RSTG 12             // k_read pipeline stages

// ---- device scratch (static allocation only; no cudaMalloc allowed) ----
__device__ float  g_dotp[DSPLIT * Bn * Nn];  // partial dots per d-split, [p][b][n]
__device__ float  g_sqp[DSPLIT * Nn];        // partial row sumsq per d-split, [p][n]
__device__ float  g_kps[Bn * DSPLIT];        // key sum partials, [b][sy]
__device__ float  g_kpq[Bn * DSPLIT];        // key sumsq partials, [b][sy]
__device__ __align__(16) float2 g_w2[Nn * Bn];  // weights, [n][b], duplicated (w,w)

// ---- packed fp32x2 FMA (sm_100+; ptxas will not auto-generate this) ----
__device__ __forceinline__ void fma2(unsigned long long& acc,
                                     unsigned long long a,
                                     unsigned long long b) {
    asm("fma.rn.f32x2 %0, %1, %2, %0;" : "+l"(acc) : "l"(a), "l"(b));
}
__device__ __forceinline__ float f2lo(unsigned long long v) {
    return __uint_as_float((unsigned)(v & 0xFFFFFFFFull));
}
__device__ __forceinline__ float f2hi(unsigned long long v) {
    return __uint_as_float((unsigned)(v >> 32));
}

// ---- cp.async (LDGSTS) helpers ----
__device__ __forceinline__ void cp16(void* smem, const void* gmem) {
    unsigned s = (unsigned)__cvta_generic_to_shared(smem);
    asm volatile("cp.async.cg.shared.global [%0], [%1], 16;" :: "r"(s), "l"(gmem));
}
__device__ __forceinline__ void cp_commit() {
    asm volatile("cp.async.commit_group;");
}
template <int N>
__device__ __forceinline__ void cp_wait() {
    asm volatile("cp.async.wait_group %0;" :: "n"(N));
}

// ---- no-return vector atomic add ----
__device__ __forceinline__ void red_add4(float* p, float x, float y, float z, float w) {
    asm volatile("red.global.add.v4.f32 [%0], {%1, %2, %3, %4};"
                 :: "l"(p), "f"(x), "f"(y), "f"(z), "f"(w) : "memory");
}

// =======================================================================
// K2: partial dots + partial sumsq (+ fused key stats in x==0 blocks).
// grid (125, 7) x 256 threads. Block owns 16 memory rows, 14 d-chunks of
// 256 floats (d-split by grid.y). Key chunk (16x256) and mem chunk (16x256)
// staged via 3-slot cp.async ring: ONE wait + ONE barrier + ONE commit
// group per chunk (14 barriers/block; ~2 chunks = 32KB in flight).
// Dynamic smem: 3 x 32KB = 96KB; 2 blocks/SM (192KB).
// Lane layout per warp: bit7=bh (which 8 b's), bits[6:5]=u_hi, bits[4:3]=g
// (which 4 n's), bits[2:0]=u_lo. d-lane = u_hi*8+u_lo; each thread covers
// d-floats dl*4..dl*4+3 in both halves (+0, +128) of the 256-float chunk.
// g in-warp -> key LDS is a 4-way in-warp broadcast.
// =======================================================================
__global__ __launch_bounds__(256, 2) void k_dots(const float* __restrict__ key,
                                                 const float* __restrict__ mem) {
    extern __shared__ __align__(16) float sdyn[];   // KSLOT * SLOTF floats
    // overlay after the chunk loop: reduction scratch on slot 0
    float* sred = sdyn;          // 256 floats [bh][g][bb][r]
    float* ssq  = sdyn + 256;    // 16 floats  [g][r]

    int tid  = threadIdx.x;
    int bh   = tid >> 7;
    int g    = (tid >> 3) & 3;
    int u_lo = tid & 7;
    int dl   = ((tid >> 5) & 3) * 8 + u_lo;   // d-lane 0..31
    int nb   = blockIdx.x * 16;
    int sy   = blockIdx.y;
    int cbase = sy * CPB;
    bool bx0 = (blockIdx.x == 0);

    unsigned long long acc[8][4];
    #pragma unroll
    for (int i = 0; i < 8; ++i)
        #pragma unroll
        for (int r = 0; r < 4; ++r) acc[i][r] = 0ull;
    unsigned long long sq2[4] = {0ull, 0ull, 0ull, 0ull};
    float ks = 0.f, kq = 0.f;    // fused key stats (x==0 blocks only)

    // staging lanes: thread copies 2 float4 in each of 2 key + 2 mem rows
    int row0 = tid >> 5;          // 0..7
    int j    = tid & 31;          // float4 lane within first row-half

    // induction-variable global pointers (advance by CHUNK per chunk)
    const float* pk0 = key + (size_t)row0 * Dn + j * 4 + cbase * CHUNK;
    const float* pk1 = key + (size_t)(row0 + 8) * Dn + j * 4 + cbase * CHUNK;
    const float* pm0 = mem + (size_t)(nb + row0) * Dn + j * 4 + cbase * CHUNK;
    const float* pm1 = mem + (size_t)(nb + row0 + 8) * Dn + j * 4 + cbase * CHUNK;

    int so  = row0 * CHUNK + j * 4;        // smem float offset (rows 0..7)
    int so8 = (row0 + 8) * CHUNK + j * 4;  // smem float offset (rows 8..15)

    // per-thread constant compute offsets
    int mvoff = g * 4 * CHUNK + dl * 4;    // + r*CHUNK + h*128 inside
    int kvoff = bh * 8 * CHUNK + dl * 4;   // + bb*CHUNK + h*128 inside
    int ksoff = (tid >> 4) * CHUNK + (tid & 15) * 16;

    // prologue: chunks 0,1 into slots 0,1 (one commit group per chunk)
    #pragma unroll
    for (int s = 0; s < KSLOT - 1; ++s) {
        float* st = sdyn + s * SLOTF;
        const int off = s * CHUNK;
        cp16(st + so,               pk0 + off);
        cp16(st + so + 128,         pk0 + off + 128);
        cp16(st + so8,              pk1 + off);
        cp16(st + so8 + 128,        pk1 + off + 128);
        cp16(st + 4096 + so,        pm0 + off);
        cp16(st + 4096 + so + 128,  pm0 + off + 128);
        cp16(st + 4096 + so8,       pm1 + off);
        cp16(st + 4096 + so8 + 128, pm1 + off + 128);
        cp_commit();
    }

    int sb = 0;   // slot of current chunk: 0,1,2,0,...
    #pragma unroll 1
    for (int cc = 0; cc < CPB; ++cc) {
        cp_wait<1>();          // chunk cc landed (one group per chunk)
        __syncthreads();       // visible to all; fill-target slot drained

        if (cc + 2 < CPB) {    // fill chunk cc+2 into slot (sb+2)%3
            int fs = sb + 2; if (fs >= KSLOT) fs -= KSLOT;
            float* st = sdyn + fs * SLOTF;
            const float* qk0 = pk0 + 2 * CHUNK;
            const float* qk1 = pk1 + 2 * CHUNK;
            const float* qm0 = pm0 + 2 * CHUNK;
            const float* qm1 = pm1 + 2 * CHUNK;
            cp16(st + so,               qk0);
            cp16(st + so + 128,         qk0 + 128);
            cp16(st + so8,              qk1);
            cp16(st + so8 + 128,        qk1 + 128);
            cp16(st + 4096 + so,        qm0);
            cp16(st + 4096 + so + 128,  qm0 + 128);
            cp16(st + 4096 + so8,       qm1);
            cp16(st + 4096 + so8 + 128, qm1 + 128);
        }
        cp_commit();           // unconditional: keeps group accounting

        const float* km = sdyn + sb * SLOTF;
        const float* mm = km + 4096;

        #pragma unroll
        for (int h = 0; h < 2; ++h) {          // two 128-float halves
            const int hb = h * 128;
            ulonglong2 mv[4];
            #pragma unroll
            for (int r = 0; r < 4; ++r)
                mv[r] = *(const ulonglong2*)&mm[mvoff + r * CHUNK + hb];
            if (bh == 0) {
                #pragma unroll
                for (int r = 0; r < 4; ++r) {
                    fma2(sq2[r], mv[r].x, mv[r].x);
                    fma2(sq2[r], mv[r].y, mv[r].y);
                }
            }
            #pragma unroll
            for (int bb = 0; bb < 8; ++bb) {
                ulonglong2 kv = *(const ulonglong2*)&km[kvoff + bb * CHUNK + hb];
                #pragma unroll
                for (int r = 0; r < 4; ++r) {
                    fma2(acc[bb][r], kv.x, mv[r].x);
                    fma2(acc[bb][r], kv.y, mv[r].y);
                }
            }
        }

        if (bx0) {   // fused key stats: thread covers b=tid>>4, 16 d-floats
            const float* kc = km + ksoff;
            #pragma unroll
            for (int q = 0; q < 4; ++q) {
                float4 v = *(const float4*)(kc + q * 4);
                ks += (v.x + v.y) + (v.z + v.w);
                kq = fmaf(v.x, v.x, kq); kq = fmaf(v.y, v.y, kq);
                kq = fmaf(v.z, v.z, kq); kq = fmaf(v.w, v.w, kq);
            }
        }

        pk0 += CHUNK; pk1 += CHUNK; pm0 += CHUNK; pm1 += CHUNK;
        if (++sb == KSLOT) sb = 0;
    }
    __syncthreads();   // all data groups drained; safe to overlay slot 0
    sred[tid] = 0.f;   // zero overlaid reduction scratch (sred[256] + ssq[16])
    if (tid < 16) ssq[tid] = 0.f;
    __syncthreads();

    // key-stat reduce within 16-lane half-warps (same b), write per-sy partial
    if (bx0) {
        #pragma unroll
        for (int o = 1; o < 16; o <<= 1) {
            ks += __shfl_xor_sync(0xFFFFFFFFu, ks, o);
            kq += __shfl_xor_sync(0xFFFFFFFFu, kq, o);
        }
        if ((tid & 15) == 0) {
            g_kps[(tid >> 4) * DSPLIT + sy] = ks;
            g_kpq[(tid >> 4) * DSPLIT + sy] = kq;
        }
    }

    // reduce: butterfly over u_lo (8 lanes), then smem-atomic across 4 u_hi warps
    #pragma unroll
    for (int bb = 0; bb < 8; ++bb)
        #pragma unroll
        for (int r = 0; r < 4; ++r) {
            float v = f2lo(acc[bb][r]) + f2hi(acc[bb][r]);
            v += __shfl_xor_sync(0xFFFFFFFFu, v, 1);
            v += __shfl_xor_sync(0xFFFFFFFFu, v, 2);
            v += __shfl_xor_sync(0xFFFFFFFFu, v, 4);
            if (bb == u_lo)
                atomicAdd(&sred[bh * 128 + g * 32 + bb * 4 + r], v);
        }
    if (bh == 0) {
        #pragma unroll
        for (int r = 0; r < 4; ++r) {
            float v = f2lo(sq2[r]) + f2hi(sq2[r]);
            v += __shfl_xor_sync(0xFFFFFFFFu, v, 1);
            v += __shfl_xor_sync(0xFFFFFFFFu, v, 2);
            v += __shfl_xor_sync(0xFFFFFFFFu, v, 4);
            if (u_lo == r) atomicAdd(&ssq[g * 4 + r], v);
        }
    }
    __syncthreads();

    {   // write 256 partial dots
        int r = tid & 3, bb = (tid >> 2) & 7, gg = (tid >> 5) & 3, b2 = tid >> 7;
        int b = b2 * 8 + bb, n = nb + gg * 4 + r;
        g_dotp[((size_t)sy * Bn + b) * Nn + n] = sred[b2 * 128 + gg * 32 + bb * 4 + r];
    }
    if (tid < 16) {
        int r = tid & 3, gg = tid >> 2;
        g_sqp[(size_t)sy * Nn + nb + gg * 4 + r] = ssq[gg * 4 + r];
    }
}

// ============================================================
// K3: sum partials -> cos -> tan -> softmax; write transposed
// duplicated weights (w,w). Also zeroes d_out (replaces memset;
// runs before k_read in-stream). grid 16 x 256.
// ============================================================
__global__ void k_softmax(float* __restrict__ out) {
    int b = blockIdx.x, tid = threadIdx.x;
    __shared__ float sbuf[256];
    __shared__ float s_kfac;

    // zero this block's slice of the output (Bn*Dn floats over 16 blocks)
    {
        float4 z = make_float4(0.f, 0.f, 0.f, 0.f);
        float4* o4 = (float4*)(out + (size_t)b * Dn);
        for (int i = tid; i < Dn / 4; i += 256) o4[i] = z;
    }

    if (tid == 0) {
        float S = 0.f, Q = 0.f;
        #pragma unroll
        for (int p = 0; p < DSPLIT; ++p) {
            S += g_kps[b * DSPLIT + p];
            Q += g_kpq[b * DSPLIT + p];
        }
        S += 1e-7f;                                   // EPS_SUM
        // (s+eps)*kn = max(sqrt(sq_key), 1e-8*(s+eps))
        s_kfac = 1.f / fmaxf(sqrtf(Q), 1e-8f * S);
    }
    __syncthreads();
    float kf = s_kfac;

    float tv[8];
    float mx = -3.4e38f;
    #pragma unroll
    for (int i = 0; i < 8; ++i) {
        int n = tid + i * 256;
        if (n < Nn) {
            float dot = 0.f, sqv = 0.f;
            #pragma unroll
            for (int p = 0; p < DSPLIT; ++p) {
                dot += g_dotp[((size_t)p * Bn + b) * Nn + n];
                sqv += g_sqp[(size_t)p * Nn + n];
            }
            float mn = fmaxf(sqrtf(sqv), 1e-8f);
            float cosv = dot * kf / mn;
            float t = tanf(cosv * PI2F);
            tv[i] = t;
            mx = fmaxf(mx, t);
        } else tv[i] = -3.4e38f;
    }
    sbuf[tid] = mx; __syncthreads();
    for (int s = 128; s; s >>= 1) {
        if (tid < s) sbuf[tid] = fmaxf(sbuf[tid], sbuf[tid + s]);
        __syncthreads();
    }
    mx = sbuf[0];
    __syncthreads();

    float sum = 0.f;
    #pragma unroll
    for (int i = 0; i < 8; ++i) {
        int n = tid + i * 256;
        if (n < Nn) { float e = expf(tv[i] - mx); tv[i] = e; sum += e; }
    }
    sbuf[tid] = sum; __syncthreads();
    for (int s = 128; s; s >>= 1) {
        if (tid < s) sbuf[tid] += sbuf[tid + s];
        __syncthreads();
    }
    float inv = 1.f / sbuf[0];

    #pragma unroll
    for (int i = 0; i < 8; ++i) {
        int n = tid + i * 256;
        if (n < Nn) {
            float w = tv[i] * inv;
            g_w2[(size_t)n * Bn + b] = make_float2(w, w);  // pre-duplicated pair
        }
    }
}

// =======================================================================
// K4: out[b][d] = sum_n w[b][n] * mem[n][d]. grid (49, 12) x 128 threads.
// 588 blocks = exactly one occ-4 wave (592 slots on 148 SMs).
// Thread owns 4 consecutive d; 16 b accumulators as f32x2 pairs.
// Mem rows flow through a per-thread 12-stage cp.async pipeline (11 rows of
// DRAM latency in flight, no barriers). Weight tile staged in smem once.
// Partials combined via red.global.add.v4.f32 (no-return vector atomic).
// =======================================================================
__global__ __launch_bounds__(128, 4) void k_read(const float* __restrict__ mem,
                                                 float* __restrict__ out) {
    __shared__ __align__(16) ulonglong2 sw[167 * 8];     // 21376 B weight tile
    __shared__ __align__(16) char smrow[RSTG][2048];     // 24 KB pipeline

    int tid = threadIdx.x;
    int d   = blockIdx.x * 512 + tid * 4;
    int y   = blockIdx.y;
    int n0  = (y < 8) ? y * 167 : 1336 + (y - 8) * 166;
    int cnt = (y < 8) ? 167 : 166;

    // stage weight tile: cnt x 128B
    {
        const float4* src = (const float4*)(g_w2 + (size_t)n0 * Bn);
        for (int i = tid; i < cnt * 8; i += 128)
            ((float4*)sw)[i] = src[i];
    }

    unsigned long long acc[16][2];
    #pragma unroll
    for (int b = 0; b < 16; ++b) { acc[b][0] = 0ull; acc[b][1] = 0ull; }

    const float* mp = mem + (size_t)n0 * Dn + d;
    // prologue: 11 rows in flight (cnt >= 166 always)
    #pragma unroll
    for (int s = 0; s < RSTG - 1; ++s) {
        cp16(&smrow[s][tid * 16], mp + (size_t)s * Dn);
        cp_commit();
    }
    const float* pf = mp + (size_t)(RSTG - 1) * Dn;
    __syncthreads();   // weight tile ready

    int slc = 0, sli = RSTG - 1;
    for (int n = 0; n < cnt; ++n) {
        cp_wait<RSTG - 2>();  // per-thread: stage n landed
        ulonglong2 cur = *(const ulonglong2*)&smrow[slc][tid * 16];
        if (++slc == RSTG) slc = 0;
        if (n + RSTG - 1 < cnt) cp16(&smrow[sli][tid * 16], pf);
        cp_commit();
        if (++sli == RSTG) sli = 0;
        pf += Dn;
        const ulonglong2* wq = sw + n * 8;
        #pragma unroll
        for (int q = 0; q < 8; ++q) {
            ulonglong2 wv = wq[q];                // (w2q,w2q),(w2q+1,w2q+1)
            fma2(acc[2 * q    ][0], wv.x, cur.x);
            fma2(acc[2 * q    ][1], wv.x, cur.y);
            fma2(acc[2 * q + 1][0], wv.y, cur.x);
            fma2(acc[2 * q + 1][1], wv.y, cur.y);
        }
    }

    #pragma unroll
    for (int b = 0; b < 16; ++b) {
        float* o = out + (size_t)b * Dn + d;
        red_add4(o, f2lo(acc[b][0]), f2hi(acc[b][0]),
                    f2lo(acc[b][1]), f2hi(acc[b][1]));
    }
}

// ============================================================
extern "C" void kernel_launch(void* const* d_in, const int* in_sizes, int n_in,
                              void* d_out, int out_size) {
    const float* key = (const float*)d_in[0];
    const float* mem = (const float*)d_in[1];
    // metadata order is key, memory; swap defensively if sizes say otherwise
    if (n_in >= 2 && in_sizes[0] == Nn * Dn) {
        key = (const float*)d_in[1];
        mem = (const float*)d_in[0];
    }
    float* out = (float*)d_out;

    // 96KB dynamic smem for k_dots (attribute persists from the harness's
    // non-captured correctness call, so capture-time behavior is identical)
    const int kdots_smem = KSLOT * SLOTF * (int)sizeof(float);
    cudaFuncSetAttribute(k_dots, cudaFuncAttributeMaxDynamicSharedMemorySize,
                         kdots_smem);

    k_dots<<<dim3(125, DSPLIT), 256, kdots_smem>>>(key, mem);
    k_softmax<<<16, 256>>>(out);   // also zeroes out before k_read's red.adds
    k_read<<<dim3(49, 12), 128>>>(mem, out);
}